// round 3
// baseline (speedup 1.0000x reference)
#include <cuda_runtime.h>
#include <cuda_bf16.h>

// CoverageLoss:
//   loss = sum_{f,fp} min_b ( outside(f,fp,b) * min_bp ||frag - boxpt(b,bp)||^2 ) / FP
// Shapes: pred[64,4], fragments[32,64,2] (2048 points), boundary[400,2].
//
// Inner distance expanded:  ||f-b||^2 = (fx^2+fy^2) + (bx^2+by^2) - 2fx*bx - 2fy*by
// -> per (point, boundary-pt): 2 FFMA (fma pipe) + 1 FMNMX (alu pipe).
// min over boxes via atomicMin on uint bit pattern (valid for non-negative floats).

#define NPTS    2048      // F*FP = 32*64 fragment points
#define BPTOT   400       // boundary samples per box
#define CHUNK   200       // boundary points per block
#define NCHUNK  2         // BPTOT / CHUNK
#define NBOX    64
#define PPT     8         // fragment points per thread
#define THREADS 256       // PPT * THREADS = NPTS
#define FP_DIV  64.0f     // fragments.shape[1]

__device__ unsigned int g_min[NPTS];

__global__ void cl_init_kernel() {
    int i = blockIdx.x * blockDim.x + threadIdx.x;
    if (i < NPTS) g_min[i] = 0x7f800000u;  // +inf
}

__global__ __launch_bounds__(THREADS)
void cl_dist_kernel(const float* __restrict__ pred,
                    const float* __restrict__ frag,
                    const float* __restrict__ boundary) {
    __shared__ float4 s_box[CHUNK];   // (bx, by, bx^2+by^2, pad)

    const int b     = blockIdx.y;     // box index
    const int chunk = blockIdx.x;     // boundary chunk
    const int tid   = threadIdx.x;

    const float lx = pred[4 * b + 0];
    const float ly = pred[4 * b + 1];
    const float hx = pred[4 * b + 2];
    const float hy = pred[4 * b + 3];
    const float wx = hx - lx;
    const float wy = hy - ly;

    // Build this chunk's box-boundary points in shared.
    if (tid < CHUNK) {
        int j = chunk * CHUNK + tid;
        float bx = fmaf(boundary[2 * j + 0], wx, lx);
        float by = fmaf(boundary[2 * j + 1], wy, ly);
        s_box[tid] = make_float4(bx, by, fmaf(bx, bx, by * by), 0.0f);
    }
    __syncthreads();

    // Per-thread fragment-point state.
    float nfx[PPT], nfy[PPT], m[PPT], fxy2[PPT];
    int   inside[PPT];
#pragma unroll
    for (int i = 0; i < PPT; i++) {
        int p = tid + i * THREADS;
        float fx = frag[2 * p + 0];
        float fy = frag[2 * p + 1];
        nfx[i]  = -2.0f * fx;
        nfy[i]  = -2.0f * fy;
        fxy2[i] = fmaf(fx, fx, fy * fy);
        m[i]    = 3.4e38f;
        // reference: inside iff fx>=lx && fy>=ly && hx>=fx && hy>=fy
        inside[i] = (fx >= lx) && (fy >= ly) && (hx >= fx) && (hy >= fy);
    }

    // Main loop: 1 LDS.128 broadcast + 8 x (2 FFMA + 1 FMNMX) per boundary pt.
#pragma unroll 4
    for (int j = 0; j < CHUNK; j++) {
        float4 bb = s_box[j];
#pragma unroll
        for (int i = 0; i < PPT; i++) {
            float t = fmaf(nfx[i], bb.x, bb.z);
            t       = fmaf(nfy[i], bb.y, t);
            m[i]    = fminf(m[i], t);
        }
    }

    // Commit: min over (box, chunk) via uint atomicMin (values are >= 0).
#pragma unroll
    for (int i = 0; i < PPT; i++) {
        int p = tid + i * THREADS;
        float val = inside[i] ? 0.0f : fmaxf(m[i] + fxy2[i], 0.0f);
        atomicMin(&g_min[p], __float_as_uint(val));
    }
}

__global__ void cl_reduce_kernel(float* __restrict__ out) {
    __shared__ float s_part[8];
    int tid = threadIdx.x;
    float sum = 0.0f;
#pragma unroll
    for (int i = tid; i < NPTS; i += 256)
        sum += __uint_as_float(g_min[i]);
#pragma unroll
    for (int o = 16; o > 0; o >>= 1)
        sum += __shfl_down_sync(0xffffffffu, sum, o);
    if ((tid & 31) == 0) s_part[tid >> 5] = sum;
    __syncthreads();
    if (tid < 8) {
        sum = s_part[tid];
#pragma unroll
        for (int o = 4; o > 0; o >>= 1)
            sum += __shfl_down_sync(0x000000ffu, sum, o);
        if (tid == 0) out[0] = sum * (1.0f / FP_DIV);
    }
}

extern "C" void kernel_launch(void* const* d_in, const int* in_sizes, int n_in,
                              void* d_out, int out_size) {
    const float* pred     = (const float*)d_in[0];   // [64,4]
    const float* frag     = (const float*)d_in[1];   // [32,64,2]
    const float* boundary = (const float*)d_in[2];   // [1,400,2]
    float* out = (float*)d_out;

    cl_init_kernel<<<(NPTS + 255) / 256, 256>>>();
    cl_dist_kernel<<<dim3(NCHUNK, NBOX), THREADS>>>(pred, frag, boundary);
    cl_reduce_kernel<<<1, 256>>>(out);
}

// round 7
// speedup vs baseline: 2.4449x; 2.4449x over previous
#include <cuda_runtime.h>
#include <cuda_bf16.h>

// CoverageLoss, fused single-kernel closed-ish form.
//
// Boundary samples are 4 axis-aligned uniform segments of the box:
//   vertical edges:   x in {lx, wx+lx},  y_j = lins[j]*wy + ly   (j = 0..99)
//   horizontal edges: y in {ly, wy+ly},  x_i = lins[i]*wx + lx   (i = 0..99)
// min over an edge separates:  min_j (fx-ex)^2 + (fy-y_j)^2 = (fx-ex)^2 + min_j (fy-y_j)^2
// and the grid argmin is clamp(round((fy-ly)*99/wy)); a +/-1 candidate window
// absorbs any 1-ulp nonuniformity of linspace. Exact lins[] values are read
// from the boundary input so candidate distances match the reference samples.
//
// Thread = (fragment point, box). 512 blocks x 256 threads (4 pts x 64 boxes
// per block). Per-point min over boxes via warp shuffle; one atomicAdd per
// block; last block writes out and resets scratch (graph-replay safe).

#define NPTS  2048
#define NBOX  64
#define NBLK  (NPTS / 4)      // 512 blocks, 4 points per block
#define NLIN  100

__device__ float        g_sum = 0.0f;   // static zero-init; reset by last block
__device__ unsigned int g_cnt = 0u;

__global__ __launch_bounds__(256)
void cl_fused_kernel(const float* __restrict__ pred,
                     const float* __restrict__ frag,
                     const float* __restrict__ boundary,
                     float* __restrict__ out) {
    __shared__ float s_lins[NLIN];
    __shared__ float s_warp[8];

    const int tid = threadIdx.x;
    if (tid < NLIN) s_lins[tid] = boundary[2 * tid + 1];  // a-part y-coords = lins
    __syncthreads();

    const int b  = tid & 63;          // box
    const int pl = tid >> 6;          // point-in-block 0..3 (one per warp pair)
    const int pt = blockIdx.x * 4 + pl;

    const float fx = frag[2 * pt + 0];
    const float fy = frag[2 * pt + 1];

    const float4 pr = ((const float4*)pred)[b];
    const float lx = pr.x, ly = pr.y, hx = pr.z, hy = pr.w;
    const float wx = hx - lx;
    const float wy = hy - ly;

    const bool inside = (fx >= lx) && (fy >= ly) && (hx >= fx) && (hy >= fy);

    // ---- vertical edges: x fixed, min over y samples ----
    const float dyl = fy - ly;
    float ty = dyl * 99.0f * __frcp_rn(wy);
    float jf = fminf(fmaxf(rintf(ty), 0.0f), 99.0f);   // NaN-safe: fmaxf(NaN,0)=0
    int   j  = (int)jf;
    int   j0 = max(j - 1, 0), j2 = min(j + 1, NLIN - 1);

    float d, mdy2;
    d = fy - (s_lins[j ] * wy + ly); mdy2 = d * d;
    d = fy - (s_lins[j0] * wy + ly); mdy2 = fminf(mdy2, d * d);
    d = fy - (s_lins[j2] * wy + ly); mdy2 = fminf(mdy2, d * d);

    const float dxl = fx - lx;
    const float dxh = fx - (wx + lx);   // right edge x as the reference computes it
    const float dvert = fminf(dxl * dxl, dxh * dxh) + mdy2;

    // ---- horizontal edges: y fixed, min over x samples ----
    float tx = dxl * 99.0f * __frcp_rn(wx);
    float kf = fminf(fmaxf(rintf(tx), 0.0f), 99.0f);
    int   k  = (int)kf;
    int   k0 = max(k - 1, 0), k2 = min(k + 1, NLIN - 1);

    float mdx2;
    d = fx - (s_lins[k ] * wx + lx); mdx2 = d * d;
    d = fx - (s_lins[k0] * wx + lx); mdx2 = fminf(mdx2, d * d);
    d = fx - (s_lins[k2] * wx + lx); mdx2 = fminf(mdx2, d * d);

    const float dyh = fy - (wy + ly);
    const float dhorz = fminf(dyl * dyl, dyh * dyh) + mdx2;

    float val = inside ? 0.0f : fminf(dvert, dhorz);

    // ---- min over 64 boxes: warp reduce (32 boxes/warp), pair via shared ----
#pragma unroll
    for (int o = 16; o > 0; o >>= 1)
        val = fminf(val, __shfl_xor_sync(0xffffffffu, val, o));
    if ((tid & 31) == 0) s_warp[tid >> 5] = val;
    __syncthreads();

    if (tid == 0) {
        float s = 0.0f;
#pragma unroll
        for (int p = 0; p < 4; p++)
            s += fminf(s_warp[2 * p], s_warp[2 * p + 1]);
        atomicAdd(&g_sum, s);
        __threadfence();
        unsigned done = atomicAdd(&g_cnt, 1u);
        if (done == NBLK - 1) {
            float tot = atomicAdd(&g_sum, 0.0f);   // atomic read-back
            out[0] = tot * (1.0f / 64.0f);         // / FP
            g_sum = 0.0f;                          // restore invariant for next replay
            g_cnt = 0u;
        }
    }
}

extern "C" void kernel_launch(void* const* d_in, const int* in_sizes, int n_in,
                              void* d_out, int out_size) {
    const float* pred     = (const float*)d_in[0];   // [64,4]
    const float* frag     = (const float*)d_in[1];   // [32,64,2]
    const float* boundary = (const float*)d_in[2];   // [1,400,2]
    cl_fused_kernel<<<NBLK, 256>>>(pred, frag, boundary, (float*)d_out);
}

// round 8
// speedup vs baseline: 2.8937x; 1.1836x over previous
#include <cuda_runtime.h>
#include <cuda_bf16.h>

// CoverageLoss, fused single-kernel, edge-separable closed form.
//
// Boundary samples are 4 axis-aligned uniform segments of the box; min over an
// edge separates into (perp dist)^2 + min_j (parallel dist)^2, and the grid
// argmin is clamp(round(t*99)) with a +/-1 candidate window evaluated against
// the exact lins[] values read from the boundary input.
//
// R7 layout: 128 blocks (single wave) x 256 threads; thread = (box, 4 points).
// Box constants (incl. both MUFU rcp) hoisted per thread; 4-way ILP across
// points. One atomicAdd per block; last block writes out + resets scratch.

#define NPTS  2048
#define NBOX  64
#define PPTH  4                       // points per thread
#define NBLK  (NPTS / (PPTH * 4))     // 128 blocks, 16 points per block
#define NLIN  100

__device__ float        g_sum = 0.0f;   // static zero-init; reset by last block
__device__ unsigned int g_cnt = 0u;

__global__ __launch_bounds__(256)
void cl_fused_kernel(const float* __restrict__ pred,
                     const float* __restrict__ frag,
                     const float* __restrict__ boundary,
                     float* __restrict__ out) {
    __shared__ float s_lins[NLIN];
    __shared__ float s_red[8][PPTH];

    const int tid = threadIdx.x;
    if (tid < NLIN) s_lins[tid] = boundary[2 * tid + 1];  // a-part y coords = lins
    __syncthreads();

    const int b  = tid & 63;          // box index
    const int pl = tid >> 6;          // point-slot 0..3 (two warps per slot)

    // ---- box constants (hoisted: reused across 4 points) ----
    const float4 pr = ((const float4*)pred)[b];
    const float lx = pr.x, ly = pr.y, hx = pr.z, hy = pr.w;
    const float wx = hx - lx;
    const float wy = hy - ly;
    const float ex = wx + lx;          // right-edge x as the reference computes it
    const float ey = wy + ly;          // top-edge y
    const float rwx = __frcp_rn(wx);
    const float rwy = __frcp_rn(wy);

    // ---- 4 fragment points, contiguous: 2x float4 loads ----
    const int pbase = blockIdx.x * 16 + pl * PPTH;
    const float4 f01 = ((const float4*)frag)[pbase / 2];
    const float4 f23 = ((const float4*)frag)[pbase / 2 + 1];
    float fxs[PPTH] = {f01.x, f01.z, f23.x, f23.z};
    float fys[PPTH] = {f01.y, f01.w, f23.y, f23.w};

    float vals[PPTH];
#pragma unroll
    for (int i = 0; i < PPTH; i++) {
        const float fx = fxs[i], fy = fys[i];
        const bool inside = (fx >= lx) && (fy >= ly) && (hx >= fx) && (hy >= fy);

        // vertical edges: x fixed, min over y samples
        const float dyl = fy - ly;
        float jf = fminf(fmaxf(rintf(dyl * 99.0f * rwy), 0.0f), 99.0f);  // NaN->0
        int   j  = (int)jf;
        int   j0 = max(j - 1, 0), j2 = min(j + 1, NLIN - 1);
        float d, mdy2;
        d = fy - (s_lins[j ] * wy + ly); mdy2 = d * d;
        d = fy - (s_lins[j0] * wy + ly); mdy2 = fminf(mdy2, d * d);
        d = fy - (s_lins[j2] * wy + ly); mdy2 = fminf(mdy2, d * d);
        const float dxl = fx - lx;
        const float dxh = fx - ex;
        const float dvert = fminf(dxl * dxl, dxh * dxh) + mdy2;

        // horizontal edges: y fixed, min over x samples
        float kf = fminf(fmaxf(rintf(dxl * 99.0f * rwx), 0.0f), 99.0f);
        int   k  = (int)kf;
        int   k0 = max(k - 1, 0), k2 = min(k + 1, NLIN - 1);
        float mdx2;
        d = fx - (s_lins[k ] * wx + lx); mdx2 = d * d;
        d = fx - (s_lins[k0] * wx + lx); mdx2 = fminf(mdx2, d * d);
        d = fx - (s_lins[k2] * wx + lx); mdx2 = fminf(mdx2, d * d);
        const float dyh = fy - ey;
        const float dhorz = fminf(dyl * dyl, dyh * dyh) + mdx2;

        vals[i] = inside ? 0.0f : fminf(dvert, dhorz);
    }

    // ---- min over 64 boxes: shuffle within warp (32 boxes), pair via shared ----
#pragma unroll
    for (int o = 16; o > 0; o >>= 1) {
#pragma unroll
        for (int i = 0; i < PPTH; i++)
            vals[i] = fminf(vals[i], __shfl_xor_sync(0xffffffffu, vals[i], o));
    }
    if ((tid & 31) == 0) {
        const int w = tid >> 5;
#pragma unroll
        for (int i = 0; i < PPTH; i++) s_red[w][i] = vals[i];
    }
    __syncthreads();

    if (tid == 0) {
        float s = 0.0f;
#pragma unroll
        for (int p = 0; p < 4; p++)
#pragma unroll
            for (int i = 0; i < PPTH; i++)
                s += fminf(s_red[2 * p][i], s_red[2 * p + 1][i]);
        atomicAdd(&g_sum, s);
        __threadfence();
        unsigned done = atomicAdd(&g_cnt, 1u);
        if (done == NBLK - 1) {
            float tot = atomicAdd(&g_sum, 0.0f);   // atomic read-back
            out[0] = tot * (1.0f / 64.0f);         // / FP
            g_sum = 0.0f;                          // restore invariant for replay
            g_cnt = 0u;
        }
    }
}

extern "C" void kernel_launch(void* const* d_in, const int* in_sizes, int n_in,
                              void* d_out, int out_size) {
    const float* pred     = (const float*)d_in[0];   // [64,4]
    const float* frag     = (const float*)d_in[1];   // [32,64,2]
    const float* boundary = (const float*)d_in[2];   // [1,400,2]
    cl_fused_kernel<<<NBLK, 256>>>(pred, frag, boundary, (float*)d_out);
}